// round 11
// baseline (speedup 1.0000x reference)
#include <cuda_runtime.h>
#include <cuda_bf16.h>
#include <math_constants.h>

// Problem constants (fixed: B=4, N=M=8192, C=3, k=16)
#define BB 4
#define NN 8192
#define MM 8192
#define KK 16
#define NQ (BB * NN)                 // 32768 (== BB*MM, exploited below)

// Grid
#define G 32
#define G3 (G * G * G)               // 32768 cells per batch
#define XMIN (-4.0f)
#define H 0.25f
#define INVH 4.0f

// Static scratch
__device__ int    g_pcount[BB * G3];
__device__ int    g_qcount[BB * G3];
__device__ int    g_pstart[BB * (G3 + 1)];
__device__ int    g_pcur[BB * G3];
__device__ int    g_qcur[BB * G3];
__device__ float4 g_pts[BB * MM];    // cell-sorted candidates (x,y,z,-0.5*|p|^2)
__device__ int    g_pix[BB * MM];    // original (per-batch) candidate index
__device__ int    g_qs[NQ];          // cell-sorted local query ids

__device__ __forceinline__ int cellof(float v) {
    int c = (int)floorf((v - XMIN) * INVH);
    return min(G - 1, max(0, c));
}

// Exact reference-rounded d2 (identical arithmetic to all passing rounds).
// p.w = -0.5*n2 exactly (power-of-two multiply), so n2 = -2*p.w is bit-exact.
__device__ __forceinline__ float dist2x(float4 p, float x, float y, float z, float n1) {
    float dot = __fmaf_rn(z, p.z, __fmaf_rn(y, p.y, __fmul_rn(x, p.x)));
    float n2  = __fmul_rn(-2.0f, p.w);
    return __fadd_rn(__fadd_rn(__fmul_rn(-2.0f, dot), n1), n2);
}

// Lexicographic (d2, idx) comparison — selection is order-independent.
#define LESSK(ad, ai, bd, bi) ((ad) < (bd) || ((ad) == (bd) && (ai) < (bi)))

#define INSERT16X(d2v, civ)                                               \
    do {                                                                  \
        _Pragma("unroll")                                                 \
        for (int jj = KK - 1; jj > 0; --jj) {                             \
            bool sh = LESSK(d2v, civ, dk[jj - 1], idv[jj - 1]);           \
            bool he = (!sh) && LESSK(d2v, civ, dk[jj], idv[jj]);          \
            float nd = sh ? dk[jj - 1] : (he ? (d2v) : dk[jj]);           \
            int   ni = sh ? idv[jj - 1] : (he ? (civ) : idv[jj]);         \
            dk[jj] = nd; idv[jj] = ni;                                    \
        }                                                                 \
        if (LESSK(d2v, civ, dk[0], idv[0])) { dk[0] = (d2v); idv[0] = (civ); } \
    } while (0)

// ---------------------------------------------------------------------------
// Binning kernels
// ---------------------------------------------------------------------------
__global__ void knn_zero() {
    int t = blockIdx.x * blockDim.x + threadIdx.x;
    if (t < BB * G3) { g_pcount[t] = 0; g_qcount[t] = 0; }
}

__global__ void knn_count(const float* __restrict__ xyz1,
                          const float* __restrict__ xyz2) {
    int t = blockIdx.x * blockDim.x + threadIdx.x;
    if (t < BB * MM) {
        int b = t >> 13;
        int cp = (cellof(xyz2[3 * t + 2]) * G + cellof(xyz2[3 * t + 1])) * G
                 + cellof(xyz2[3 * t + 0]);
        atomicAdd(&g_pcount[b * G3 + cp], 1);
        int cq = (cellof(xyz1[3 * t + 2]) * G + cellof(xyz1[3 * t + 1])) * G
                 + cellof(xyz1[3 * t + 0]);
        atomicAdd(&g_qcount[b * G3 + cq], 1);
    }
}

// 8 blocks: 0-3 = point grids, 4-7 = query grids. 1024 threads, 32 cells each.
__global__ void knn_scan() {
    __shared__ int part[1024];
    const int which = blockIdx.x;
    const int b = which & 3;
    const bool isQ = which >= 4;
    const int* cnt = (isQ ? g_qcount : g_pcount) + b * G3;
    int* start = isQ ? 0 : (g_pstart + b * (G3 + 1));
    int* cur = (isQ ? g_qcur : g_pcur) + b * G3;

    const int t = threadIdx.x;
    const int PER = G3 / 1024;        // 32
    const int base = t * PER;
    int s = 0;
#pragma unroll
    for (int i = 0; i < PER; ++i) s += cnt[base + i];
    part[t] = s;
    __syncthreads();
    for (int d = 1; d < 1024; d <<= 1) {
        int add = (t >= d) ? part[t - d] : 0;
        __syncthreads();
        part[t] += add;
        __syncthreads();
    }
    int off = part[t] - s;            // exclusive prefix
    for (int i = 0; i < PER; ++i) {
        if (start) start[base + i] = off;
        cur[base + i] = off;
        off += cnt[base + i];
    }
    if (start && t == 1023) start[G3] = off;
}

__global__ void knn_scatter(const float* __restrict__ xyz1,
                            const float* __restrict__ xyz2) {
    int t = blockIdx.x * blockDim.x + threadIdx.x;
    if (t < BB * MM) {
        int b = t >> 13;
        // point: pack with w = -0.5 * ((x*x+y*y)+z*z)   (reference rounding)
        float x = xyz2[3 * t + 0], y = xyz2[3 * t + 1], z = xyz2[3 * t + 2];
        float n = __fadd_rn(__fadd_rn(__fmul_rn(x, x), __fmul_rn(y, y)),
                            __fmul_rn(z, z));
        int cp = (cellof(z) * G + cellof(y)) * G + cellof(x);
        int pos = atomicAdd(&g_pcur[b * G3 + cp], 1);
        g_pts[b * MM + pos] = make_float4(x, y, z, __fmul_rn(-0.5f, n));
        g_pix[b * MM + pos] = t & (MM - 1);
        // query
        float qx = xyz1[3 * t + 0], qy = xyz1[3 * t + 1], qz = xyz1[3 * t + 2];
        int cq = (cellof(qz) * G + cellof(qy)) * G + cellof(qx);
        int qpos = atomicAdd(&g_qcur[b * G3 + cq], 1);
        g_qs[b * NN + qpos] = t & (NN - 1);
    }
}

// ---------------------------------------------------------------------------
// Main: thread per (cell-sorted) query. Expanding-cube exact KNN over the
// batch point set resident in dynamic SMEM. Certify: all unprocessed cells
// lie at distance >= margin; stop when dk[15] <= margin^2 - eps.
// ---------------------------------------------------------------------------
__global__ void __launch_bounds__(256) knn_query(const float* __restrict__ xyz1,
                                                 float* __restrict__ out,
                                                 int write_both) {
    extern __shared__ char smraw[];
    float4* tp  = (float4*)smraw;                 // 8192 candidates, 128 KB
    int*    tix = (int*)(smraw + MM * 16);        // 32 KB

    const int b = blockIdx.x >> 5;                // 32 blocks per batch
    const int tid = threadIdx.x;

    const float4* __restrict__ ps = g_pts + b * MM;
    const int*    __restrict__ px = g_pix + b * MM;
    for (int i = tid; i < MM; i += 256) { tp[i] = ps[i]; tix[i] = px[i]; }
    __syncthreads();

    const int ql = g_qs[b * NN + (blockIdx.x & 31) * 256 + tid]; // local qid
    const int qg = b * NN + ql;
    const float x = xyz1[3 * qg + 0];
    const float y = xyz1[3 * qg + 1];
    const float z = xyz1[3 * qg + 2];
    const float n1 = __fadd_rn(__fadd_rn(__fmul_rn(x, x), __fmul_rn(y, y)),
                               __fmul_rn(z, z));
    const int cx = cellof(x), cy = cellof(y), cz = cellof(z);

    const int* __restrict__ cs = g_pstart + b * (G3 + 1);
    const int* __restrict__ cc = g_pcount + b * G3;

    float dk[KK];
    int   idv[KK];
#pragma unroll
    for (int i = 0; i < KK; ++i) { dk[i] = CUDART_INF_F; idv[i] = 0x7fffffff; }

    for (int rho = 0; rho <= G; ++rho) {
        const int zlo = max(cz - rho, 0), zhi = min(cz + rho, G - 1);
        const int ylo = max(cy - rho, 0), yhi = min(cy + rho, G - 1);
        const int xlo = max(cx - rho, 0), xhi = min(cx + rho, G - 1);
        for (int iz = zlo; iz <= zhi; ++iz) {
            const int az = abs(iz - cz);
            for (int iy = ylo; iy <= yhi; ++iy) {
                const int am = max(az, abs(iy - cy));
                for (int ix = xlo; ix <= xhi; ++ix) {
                    if (max(am, abs(ix - cx)) != rho) continue;  // shell only
                    const int c = (iz * G + iy) * G + ix;
                    const int s0 = cs[c];
                    const int n  = cc[c];
                    for (int ii = 0; ii < n; ++ii) {
                        float4 p = tp[s0 + ii];
                        float d2 = dist2x(p, x, y, z, n1);
                        int ci = tix[s0 + ii];
                        if (LESSK(d2, ci, dk[KK - 1], idv[KK - 1])) {
                            INSERT16X(d2, ci);
                        }
                    }
                }
            }
        }
        // Margin to the unprocessed region (INF face when cube hits grid edge;
        // clamped out-of-range points live in edge cells, so this stays exact).
        float m = CUDART_INF_F;
        if (cx - rho > 0)     m = fminf(m, x - (XMIN + (cx - rho) * H));
        if (cx + rho < G - 1) m = fminf(m, (XMIN + (cx + rho + 1) * H) - x);
        if (cy - rho > 0)     m = fminf(m, y - (XMIN + (cy - rho) * H));
        if (cy + rho < G - 1) m = fminf(m, (XMIN + (cy + rho + 1) * H) - y);
        if (cz - rho > 0)     m = fminf(m, z - (XMIN + (cz - rho) * H));
        if (cz + rho < G - 1) m = fminf(m, (XMIN + (cz + rho + 1) * H) - z);
        if (m == CUDART_INF_F) break;                       // whole grid done
        if (m > 0.0f && dk[KK - 1] <= m * m - 1e-4f) break; // certified
    }

    // sqrt, stable (dist, idx) sort, direct write (no merge pass needed)
    float dist[KK];
#pragma unroll
    for (int i = 0; i < KK; ++i) dist[i] = __fsqrt_rn(dk[i]);

#pragma unroll
    for (int ph = 0; ph < KK; ++ph) {
#pragma unroll
        for (int i = 0; i < KK - 1; ++i) {
            if ((i & 1) == (ph & 1)) {
                bool sw = (dist[i] > dist[i + 1]) ||
                          (dist[i] == dist[i + 1] && idv[i] > idv[i + 1]);
                float td = sw ? dist[i + 1] : dist[i];
                float tD = sw ? dist[i]     : dist[i + 1];
                int   ti = sw ? idv[i + 1]  : idv[i];
                int   tI = sw ? idv[i]      : idv[i + 1];
                dist[i] = td; dist[i + 1] = tD;
                idv[i]  = ti; idv[i + 1]  = tI;
            }
        }
    }

    const long base = (long)qg * KK;
    const long off = (long)NQ * KK;
#pragma unroll
    for (int i = 0; i < KK; ++i)
        out[base + i] = dist[i];
    if (write_both) {
#pragma unroll
        for (int i = 0; i < KK; ++i)
            out[off + base + i] = (float)idv[i];
    }
}

extern "C" void kernel_launch(void* const* d_in, const int* in_sizes, int n_in,
                              void* d_out, int out_size) {
    const float* xyz1 = (const float*)d_in[0];
    const float* xyz2 = (const float*)d_in[1];
    float* out = (float*)d_out;

    int write_both = (out_size >= 2 * NQ * KK) ? 1 : 0;

    // Opt-in to 160 KB dynamic SMEM for the query kernel (idempotent).
    static bool attr_done = false;
    if (!attr_done) {
        cudaFuncSetAttribute(knn_query,
                             cudaFuncAttributeMaxDynamicSharedMemorySize,
                             MM * 16 + MM * 4);
        attr_done = true;
    }

    knn_zero<<<(BB * G3 + 255) / 256, 256>>>();
    knn_count<<<(BB * MM + 255) / 256, 256>>>(xyz1, xyz2);
    knn_scan<<<8, 1024>>>();
    knn_scatter<<<(BB * MM + 255) / 256, 256>>>(xyz1, xyz2);
    knn_query<<<128, 256, MM * 16 + MM * 4>>>(xyz1, out, write_both);
}

// round 12
// speedup vs baseline: 2.5914x; 2.5914x over previous
#include <cuda_runtime.h>
#include <cuda_bf16.h>
#include <math_constants.h>

// Problem constants (fixed: B=4, N=M=8192, C=3, k=16)
#define BB 4
#define NN 8192
#define MM 8192
#define KK 16
#define SPLIT 4
#define CHUNK (MM / SPLIT)          // 2048 candidates per mask-thread
#define SUB 512                     // sub-tile resident in smem (mask kernel)
#define NSUB (CHUNK / SUB)          // 4
#define NG 4                        // uint4 groups (128 cand) per sub-tile
#define BLOCKM 128
#define NQ (BB * NN)                // 32768 queries
#define NT (NQ * SPLIT)             // 131072 mask-threads
#define SAMPLE_M 128
#define SAMPLE_R 3                  // threshold = 3rd-closest of sample
#define SLACK 1e-3f
#define LCAP 16                     // per-lane survivor capacity (refine)
#define U64MAX 0xFFFFFFFFFFFFFFFFull

// Static scratch
__device__ float4 g_p2[BB * MM];           // packed candidates (x,y,z,-0.5*|p|^2)
__device__ uint4  g_mask[NSUB * NG * NT];  // keep-masks, [group][thread]
__device__ float  g_thr[NT];               // per-(query,chunk) Tcert

// ---------------------------------------------------------------------------
// Prep: pack xyz2 -> float4. Norm uses reference rounding ((x*x+y*y)+z*z);
// stored w = -0.5*n is EXACT (power-of-two multiply).
// ---------------------------------------------------------------------------
__global__ void knn_prep(const float* __restrict__ xyz2) {
    int t = blockIdx.x * blockDim.x + threadIdx.x;
    if (t < BB * MM) {
        float x = xyz2[3 * t + 0];
        float y = xyz2[3 * t + 1];
        float z = xyz2[3 * t + 2];
        float n = __fadd_rn(__fadd_rn(__fmul_rn(x, x), __fmul_rn(y, y)),
                            __fmul_rn(z, z));
        g_p2[t] = make_float4(x, y, z, __fmul_rn(-0.5f, n));
    }
}

// Exact reference-rounded d2 (identical arithmetic to all passing rounds).
__device__ __forceinline__ float dist2x(float4 p, float x, float y, float z, float n1) {
    float dot = __fmaf_rn(z, p.z, __fmaf_rn(y, p.y, __fmul_rn(x, p.x)));
    float n2  = __fmul_rn(-2.0f, p.w);
    return __fadd_rn(__fadd_rn(__fmul_rn(-2.0f, dot), n1), n2);
}

// Filter metric: val = dot - n2/2 (3 FMAs). Larger val == closer.
__device__ __forceinline__ float fval(float4 p, float x, float y, float z) {
    return __fmaf_rn(x, p.x, __fmaf_rn(y, p.y, __fmaf_rn(z, p.z, p.w)));
}

// Order-preserving float <-> uint transforms (total order incl. negatives).
__device__ __forceinline__ unsigned f2o(float f) {
    unsigned u = __float_as_uint(f);
    return u ^ ((u >> 31) ? 0xFFFFFFFFu : 0x80000000u);
}
__device__ __forceinline__ float o2f(unsigned u) {
    unsigned v = u ^ ((u >> 31) ? 0x80000000u : 0xFFFFFFFFu);
    return __uint_as_float(v);
}

// ---------------------------------------------------------------------------
// Kernel A: mask build (validated structure from round 8; rank-3 threshold).
// ---------------------------------------------------------------------------
__global__ void __launch_bounds__(BLOCKM, 10) knn_mask(const float* __restrict__ xyz1) {
    __shared__ float4 tile[SUB];                  // 8 KB

    const int tid  = threadIdx.x;
    const int gtid = blockIdx.x * BLOCKM + tid;
    const int s = blockIdx.x & (SPLIT - 1);
    const int q = (blockIdx.x >> 2) * BLOCKM + tid;
    const int b = q >> 13;
    const float4* __restrict__ src = g_p2 + b * MM + s * CHUNK;

    const float x = xyz1[3 * q + 0];
    const float y = xyz1[3 * q + 1];
    const float z = xyz1[3 * q + 2];
    const float n1 = __fadd_rn(__fadd_rn(__fmul_rn(x, x), __fmul_rn(y, y)),
                               __fmul_rn(z, z));

    float hqd = 0.0f;

    for (int st = 0; st < NSUB; ++st) {
        __syncthreads();
#pragma unroll
        for (int i = tid; i < SUB; i += BLOCKM)
            tile[i] = src[st * SUB + i];
        __syncthreads();

        if (st == 0) {
            // Threshold: branchless LARGEST-3 val chain over first 128 cands.
            float sl[SAMPLE_R];
#pragma unroll
            for (int i = 0; i < SAMPLE_R; ++i) sl[i] = -CUDART_INF_F;
#pragma unroll 4
            for (int j = 0; j < SAMPLE_M; ++j) {
                float v = fval(tile[j], x, y, z);
#pragma unroll
                for (int jj = SAMPLE_R - 1; jj > 0; --jj)
                    sl[jj] = fmaxf(fminf(v, sl[jj - 1]), sl[jj]);
                sl[0] = fmaxf(sl[0], v);
            }
            float hq = sl[SAMPLE_R - 1];
            hqd = hq - SLACK;
            // excluded => val < hqd => exact d2 > Tcert (SLACK >> fp error)
            g_thr[gtid] = __fadd_rn(__fmaf_rn(-2.0f, hq, n1), SLACK);
        }

        for (int g = 0; g < NG; ++g) {
            unsigned r[4];
#pragma unroll
            for (int w = 0; w < 4; ++w) {
                const int j0 = (g * 4 + w) * 32;
                unsigned m0 = 0, m1 = 0, m2 = 0, m3 = 0;
#pragma unroll
                for (int i = 0; i < 8; ++i) {
                    float v0 = fval(tile[j0 + 4 * i + 0], x, y, z);
                    float v1 = fval(tile[j0 + 4 * i + 1], x, y, z);
                    float v2 = fval(tile[j0 + 4 * i + 2], x, y, z);
                    float v3 = fval(tile[j0 + 4 * i + 3], x, y, z);
                    if (v0 >= hqd) m0 |= (1u << (4 * i + 0));
                    if (v1 >= hqd) m1 |= (1u << (4 * i + 1));
                    if (v2 >= hqd) m2 |= (1u << (4 * i + 2));
                    if (v3 >= hqd) m3 |= (1u << (4 * i + 3));
                }
                r[w] = (m0 | m1) | (m2 | m3);
            }
            g_mask[(st * NG + g) * NT + gtid] = make_uint4(r[0], r[1], r[2], r[3]);
        }
    }
}

// ---------------------------------------------------------------------------
// Kernel B: warp-per-query select. Lanes extract survivors from masks,
// build exact (d2,idx) u64 keys, bitonic-sort per lane, 16-round warp-min
// extraction. Cert failure / lane overflow -> exact in-warp full rescan.
// ---------------------------------------------------------------------------
__global__ void __launch_bounds__(256) knn_select(const float* __restrict__ xyz1,
                                                  float* __restrict__ out,
                                                  int write_both) {
    __shared__ unsigned long long col[8][LCAP][32];   // 32 KB, conflict-free

    const int w    = threadIdx.x >> 5;
    const int lane = threadIdx.x & 31;
    const int q    = blockIdx.x * 8 + w;
    const int b    = q >> 13;
    const float4* __restrict__ ps = g_p2 + b * MM;

    const float x = xyz1[3 * q + 0];
    const float y = xyz1[3 * q + 1];
    const float z = xyz1[3 * q + 2];
    const float n1 = __fadd_rn(__fadd_rn(__fmul_rn(x, x), __fmul_rn(y, y)),
                               __fmul_rn(z, z));

    // Tmin = min over the 4 chunk Tcerts (broadcast L1 loads).
    float Tmin = CUDART_INF_F;
#pragma unroll
    for (int s = 0; s < SPLIT; ++s)
        Tmin = fminf(Tmin, g_thr[((q >> 7) * SPLIT + s) * BLOCKM + (q & 127)]);

    int cnt = 0, cert = 0;

#pragma unroll
    for (int h = 0; h < 2; ++h) {
        const int gl  = lane + h * 32;        // 0..63 linear group per query
        const int s   = gl >> 4;              // chunk
        const int g16 = gl & 15;              // group within chunk
        const int st  = g16 >> 2;
        const int g   = g16 & 3;
        const int gtid = ((q >> 7) * SPLIT + s) * BLOCKM + (q & 127);
        const uint4 mv = g_mask[(st * NG + g) * NT + gtid];
        const int base = s * CHUNK + st * SUB + g * 128;
        unsigned comp[4] = {mv.x, mv.y, mv.z, mv.w};
#pragma unroll
        for (int c4 = 0; c4 < 4; ++c4) {
            unsigned m = comp[c4];
            const int cb = base + c4 * 32;
            while (m) {
                int bb = __ffs(m) - 1;
                m &= m - 1;
                int ci = cb + bb;
                float4 p = ps[ci];
                float d2 = dist2x(p, x, y, z, n1);
                cert += (d2 <= Tmin);
                unsigned long long key =
                    ((unsigned long long)f2o(d2) << 32) | (unsigned)ci;
                if (cnt < LCAP) col[w][cnt][lane] = key;
                cnt++;
            }
        }
    }

    unsigned certw = __reduce_add_sync(0xFFFFFFFFu, (unsigned)cert);
    bool fb = (certw < KK) || __any_sync(0xFFFFFFFFu, cnt > LCAP);

    unsigned long long kk[LCAP];
    if (!fb) {
#pragma unroll
        for (int i = 0; i < LCAP; ++i)
            kk[i] = (i < cnt) ? col[w][i][lane] : U64MAX;
        // Bitonic sort 16 ascending (static network, register-resident).
#pragma unroll
        for (int k2 = 2; k2 <= 16; k2 <<= 1) {
#pragma unroll
            for (int j = k2 >> 1; j > 0; j >>= 1) {
#pragma unroll
                for (int i = 0; i < 16; ++i) {
                    int l = i ^ j;
                    if (l > i) {
                        bool up = ((i & k2) == 0);
                        unsigned long long a = kk[i], c = kk[l];
                        bool sw = up ? (a > c) : (a < c);
                        kk[i] = sw ? c : a;
                        kk[l] = sw ? a : c;
                    }
                }
            }
        }
    } else {
        // Exact in-warp fallback: full scan, per-lane sorted-16 insert.
#pragma unroll
        for (int i = 0; i < LCAP; ++i) kk[i] = U64MAX;
        for (int i = 0; i < MM / 32; ++i) {
            int ci = i * 32 + lane;                    // coalesced
            float4 p = ps[ci];
            float d2 = dist2x(p, x, y, z, n1);
            unsigned long long key =
                ((unsigned long long)f2o(d2) << 32) | (unsigned)ci;
            if (key < kk[LCAP - 1]) {
#pragma unroll
                for (int jj = LCAP - 1; jj > 0; --jj) {
                    bool sh = key < kk[jj - 1];
                    kk[jj] = sh ? kk[jj - 1] : ((key < kk[jj]) ? key : kk[jj]);
                }
                if (key < kk[0]) kk[0] = key;
            }
        }
    }

    // Write sorted column back; 16-round warp-min extraction.
#pragma unroll
    for (int i = 0; i < LCAP; ++i) col[w][i][lane] = kk[i];

    int hh = 0;
    unsigned long long cur = kk[0];
    unsigned long long myres = U64MAX;
#pragma unroll
    for (int r = 0; r < KK; ++r) {
        unsigned long long mn = cur;
#pragma unroll
        for (int d = 16; d > 0; d >>= 1) {
            unsigned long long o = __shfl_xor_sync(0xFFFFFFFFu, mn, d);
            mn = (o < mn) ? o : mn;
        }
        if (lane == r) myres = mn;
        if (cur == mn) {
            ++hh;
            cur = (hh < LCAP) ? col[w][hh][lane] : U64MAX;
        }
    }

    // Re-key by (sqrt(d2), idx) and odd-even transposition sort across lanes
    // 0..15 to reproduce the validated sqrt-collision tie ordering.
    float dist = __fsqrt_rn(o2f((unsigned)(myres >> 32)));
    unsigned ci = (unsigned)(myres & 0xFFFFFFFFull);
    unsigned long long key2 =
        (lane < KK) ? (((unsigned long long)f2o(dist) << 32) | ci) : U64MAX;
#pragma unroll
    for (int ph = 0; ph < KK; ++ph) {
        int odd = ph & 1;
        int mate = ((lane & 1) == odd) ? lane + 1 : lane - 1;
        bool active = (lane < KK) && (mate >= 0) && (mate < KK);
        int src = active ? mate : lane;
        unsigned long long ok = __shfl_sync(0xFFFFFFFFu, key2, src);
        if (active) {
            bool keepMin = (lane < mate);
            unsigned long long mnk = (key2 < ok) ? key2 : ok;
            unsigned long long mxk = (key2 < ok) ? ok : key2;
            key2 = keepMin ? mnk : mxk;
        }
    }

    if (lane < KK) {
        float dd = o2f((unsigned)(key2 >> 32));
        int   ii = (int)(key2 & 0xFFFFFFFFull);
        out[(long)q * KK + lane] = dd;
        if (write_both)
            out[(long)NQ * KK + (long)q * KK + lane] = (float)ii;
    }
}

extern "C" void kernel_launch(void* const* d_in, const int* in_sizes, int n_in,
                              void* d_out, int out_size) {
    const float* xyz1 = (const float*)d_in[0];
    const float* xyz2 = (const float*)d_in[1];
    float* out = (float*)d_out;

    int write_both = (out_size >= 2 * NQ * KK) ? 1 : 0;

    knn_prep<<<(BB * MM + 255) / 256, 256>>>(xyz2);
    knn_mask<<<NT / BLOCKM, BLOCKM>>>(xyz1);
    knn_select<<<NQ / 8, 256>>>(xyz1, out, write_both);
}